// round 3
// baseline (speedup 1.0000x reference)
#include <cuda_runtime.h>
#include <cuda_bf16.h>

#define BATCH 32
#define SEQ   4096
#define EMBED 512
#define HID   256
#define OUTD  128

__device__ float g_curT[HID * SEQ];     // currents TRANSPOSED [256][4096]
__device__ float g_cnt[HID];            // spike counts per hidden unit

// ---------------------------------------------------------------------------
// Kernel 1 (fused): batch-mean + GEMM.
// Grid: 256 blocks, each owns a 16-row seq tile. 512 threads.
// Phase A: xm_tile[16][512] = mean_b x[b, tile, :]  (DRAM-bound, 268MB total)
//          stored in smem as DUPLICATED float2 (v,v), k-fastest, for f32x2.
// Phase B: cur_tile[16][256] = xm_tile @ W1 with packed fma.rn.f32x2.
//          thread = (h-pair 0..127, s-group 0..3 of 4 s each).
// Output written transposed: g_curT[h][s].
// ---------------------------------------------------------------------------
#define STILE     16
#define SXD_PITCH 520    // float2 pitch per s row (512 + 8 pad)

__device__ __forceinline__ void fma2(unsigned long long& d,
                                     unsigned long long a,
                                     unsigned long long b) {
    asm("fma.rn.f32x2 %0, %1, %2, %0;" : "+l"(d) : "l"(a), "l"(b));
}

__global__ void __launch_bounds__(512, 2)
snn_fused_kernel(const float* __restrict__ x, const float* __restrict__ W1) {
    extern __shared__ float2 sXd[];   // [STILE][SXD_PITCH] duplicated pairs

    const int tid = threadIdx.x;
    const int s0  = blockIdx.x * STILE;
    const int NF4 = SEQ * EMBED / 4;          // float4 per batch

    // ---- Phase A: batch mean ----
    const float4* x4 = reinterpret_cast<const float4*>(x);
    float4 acc[4];
#pragma unroll
    for (int l = 0; l < 4; l++) acc[l] = make_float4(0.f, 0.f, 0.f, 0.f);

    const size_t base = (size_t)s0 * (EMBED / 4);
#pragma unroll 4
    for (int b = 0; b < BATCH; b++) {
        size_t boff = (size_t)b * NF4 + base;
#pragma unroll
        for (int l = 0; l < 4; l++) {
            float4 v = x4[boff + tid + l * 512];
            acc[l].x += v.x; acc[l].y += v.y; acc[l].z += v.z; acc[l].w += v.w;
        }
    }
    const float inv = 1.0f / 32.0f;
#pragma unroll
    for (int l = 0; l < 4; l++) {
        int f = tid + l * 512;        // float4 index within tile
        int s = f >> 7;               // 0..15
        int d = (f & 127) * 4;        // embed dim
        float2* row = &sXd[s * SXD_PITCH];
        float vx = acc[l].x * inv, vy = acc[l].y * inv;
        float vz = acc[l].z * inv, vw = acc[l].w * inv;
        row[d + 0] = make_float2(vx, vx);
        row[d + 1] = make_float2(vy, vy);
        row[d + 2] = make_float2(vz, vz);
        row[d + 3] = make_float2(vw, vw);
    }
    __syncthreads();

    // ---- Phase B: tile GEMM with f32x2 ----
    const int hp = tid & 127;     // h-pair index (h = 2hp, 2hp+1)
    const int sg = tid >> 7;      // s-group 0..3 (4 s each)

    const unsigned long long* Wp =
        reinterpret_cast<const unsigned long long*>(W1) + hp;   // W1[k][2hp..]
    const unsigned long long* A =
        reinterpret_cast<const unsigned long long*>(sXd) + (size_t)sg * 4 * SXD_PITCH;

    unsigned long long c2[4] = {0ull, 0ull, 0ull, 0ull};
#pragma unroll 8
    for (int k = 0; k < EMBED; k++) {
        unsigned long long w = Wp[(size_t)k * (HID / 2)];
        fma2(c2[0], A[0 * SXD_PITCH + k], w);
        fma2(c2[1], A[1 * SXD_PITCH + k], w);
        fma2(c2[2], A[2 * SXD_PITCH + k], w);
        fma2(c2[3], A[3 * SXD_PITCH + k], w);
    }

#pragma unroll
    for (int i = 0; i < 4; i++) {
        float2 v = *reinterpret_cast<float2*>(&c2[i]);
        int s = s0 + sg * 4 + i;
        g_curT[(size_t)(2 * hp)     * SEQ + s] = v.x;
        g_curT[(size_t)(2 * hp + 1) * SEQ + s] = v.y;
    }
}

// ---------------------------------------------------------------------------
// Kernel 2: epoch-parallel LIF scan. One block per hidden unit h.
// Post-spike state is always (mem=0, refr=2): accumulation restarts at
// t_spike+3; initial state == "spiked at t=-3". So:
//   1) next-spike table N(a) for every accumulation start a (4 interleaved
//      chains per thread for ILP; contiguous starts per thread for low
//      divergence)
//   2) pointer-doubling over packed (count<<13 | jump) to total the spikes.
// ---------------------------------------------------------------------------
#define DECAYF 0.95f

__global__ void __launch_bounds__(1024, 1)
snn_table_kernel(void) {
    __shared__ float    sc[SEQ + 4];   // currents row; reused as Pb in phase 2
    __shared__ unsigned Pa[SEQ + 1];

    const int h   = blockIdx.x;
    const int tid = threadIdx.x;

    reinterpret_cast<float4*>(sc)[tid] =
        reinterpret_cast<const float4*>(&g_curT[(size_t)h * SEQ])[tid];
    __syncthreads();

    // Phase 1: 4 interleaved next-spike searches, starts 4*tid..4*tid+3
    {
        float    m[4];
        int      t[4];
        unsigned res[4];
        bool     done[4];
#pragma unroll
        for (int r = 0; r < 4; r++) {
            m[r] = 0.f; t[r] = tid * 4 + r; done[r] = false; res[r] = SEQ;
        }
        int remaining = 4;
        while (remaining > 0) {
#pragma unroll
            for (int r = 0; r < 4; r++) {
                if (!done[r]) {
                    if (t[r] >= SEQ) {
                        res[r] = SEQ;            // no spike: jump to sentinel
                        done[r] = true; remaining--;
                    } else {
                        m[r] = fmaf(DECAYF, m[r], sc[t[r]]);
                        if (m[r] >= 1.0f) {
                            int j = t[r] + 3; if (j > SEQ) j = SEQ;
                            res[r] = (1u << 13) | (unsigned)j;
                            done[r] = true; remaining--;
                        } else {
                            t[r]++;
                        }
                    }
                }
            }
        }
#pragma unroll
        for (int r = 0; r < 4; r++) Pa[tid * 4 + r] = res[r];
    }
    if (tid == 0) Pa[SEQ] = (unsigned)SEQ;  // sentinel: self-loop, count 0
    __syncthreads();

    // Phase 2: pointer doubling (12 rounds covers max chain length 1366)
    unsigned* Pb   = reinterpret_cast<unsigned*>(sc);
    unsigned* srcp = Pa;
    unsigned* dstp = Pb;
#pragma unroll 1
    for (int r = 0; r < 12; r++) {
        for (int a = tid; a <= SEQ; a += 1024) {
            unsigned p = srcp[a];
            unsigned q = srcp[p & 8191u];
            dstp[a] = ((p & ~8191u) + (q & ~8191u)) | (q & 8191u);
        }
        __syncthreads();
        unsigned* tmp = srcp; srcp = dstp; dstp = tmp;
    }
    if (tid == 0) g_cnt[h] = (float)(srcp[0] >> 13);   // 12 rounds even -> Pa
}

// ---------------------------------------------------------------------------
// Kernel 3: out = (cnt @ W2) / SEQ, broadcast over batch. 512 threads,
// k split 4-way, smem reduce.
// ---------------------------------------------------------------------------
__global__ void __launch_bounds__(512, 1)
snn_out_kernel(const float* __restrict__ W2, float* __restrict__ out) {
    __shared__ float scnt[HID];
    __shared__ float part[4][OUTD];
    const int tid = threadIdx.x;
    if (tid < HID) scnt[tid] = g_cnt[tid];
    __syncthreads();

    const int j = tid & 127;   // out column
    const int g = tid >> 7;    // k-group 0..3
    float a = 0.f;
#pragma unroll 16
    for (int k = g * 64; k < g * 64 + 64; k++)
        a += scnt[k] * W2[(size_t)k * OUTD + j];
    part[g][j] = a;
    __syncthreads();

    if (tid < OUTD) {
        float s = (part[0][tid] + part[1][tid] + part[2][tid] + part[3][tid])
                  * (1.0f / (float)SEQ);
#pragma unroll
        for (int b = 0; b < BATCH; b++)
            out[(size_t)b * OUTD + tid] = s;
    }
}

// ---------------------------------------------------------------------------
extern "C" void kernel_launch(void* const* d_in, const int* in_sizes, int n_in,
                              void* d_out, int out_size) {
    const float* x  = (const float*)d_in[0];   // [32][4096][512]
    const float* w1 = (const float*)d_in[1];   // [512][256]
    const float* w2 = (const float*)d_in[2];   // [256][128]
    float* out = (float*)d_out;                // [32][128]

    const int smem = STILE * SXD_PITCH * sizeof(float2);   // 66,560 B
    static int attr_set = 0;
    if (!attr_set) {
        cudaFuncSetAttribute(snn_fused_kernel,
                             cudaFuncAttributeMaxDynamicSharedMemorySize, smem);
        attr_set = 1;
    }

    snn_fused_kernel<<<SEQ / STILE, 512, smem>>>(x, w1);
    snn_table_kernel<<<HID, 1024>>>();
    snn_out_kernel<<<1, 512>>>(w2, out);
}

// round 4
// speedup vs baseline: 1.0557x; 1.0557x over previous
#include <cuda_runtime.h>
#include <cuda_bf16.h>

#define BATCH 32
#define SEQ   4096
#define EMBED 512
#define HID   256
#define OUTD  128

__device__ float g_xm[SEQ * EMBED];     // batch-mean  [4096][512]
__device__ float g_curT[HID * SEQ];     // currents TRANSPOSED [256][4096]
__device__ float g_cnt[HID];            // spike counts per hidden unit

// ---------------------------------------------------------------------------
// Kernel 1: batch mean over B=32.  x: [32][4096][512] -> xm: [4096][512]
// ---------------------------------------------------------------------------
__global__ void snn_mean_kernel(const float* __restrict__ x) {
    const int NF4 = (SEQ * EMBED) / 4;
    int i = blockIdx.x * blockDim.x + threadIdx.x;
    if (i >= NF4) return;
    const float4* x4 = reinterpret_cast<const float4*>(x);
    float sx = 0.f, sy = 0.f, sz = 0.f, sw = 0.f;
#pragma unroll
    for (int b = 0; b < BATCH; b++) {
        float4 v = x4[(size_t)b * NF4 + i];
        sx += v.x; sy += v.y; sz += v.z; sw += v.w;
    }
    const float inv = 1.0f / 32.0f;
    float4 r; r.x = sx * inv; r.y = sy * inv; r.z = sz * inv; r.w = sw * inv;
    reinterpret_cast<float4*>(g_xm)[i] = r;
}

// ---------------------------------------------------------------------------
// Kernel 2: SGEMM currents = xm @ W1, f32x2 packed FMA, transposed output.
// 64x64 tile, BK=32, 4x4 micro-tile (packed as 4x2 f32x2), 256 threads.
// ---------------------------------------------------------------------------
#define BM 64
#define BN 64
#define BK 32
#define SA_STRIDE 136

__device__ __forceinline__ void fma2(unsigned long long& d,
                                     unsigned long long a,
                                     unsigned long long b) {
    asm("fma.rn.f32x2 %0, %1, %2, %0;" : "+l"(d) : "l"(a), "l"(b));
}

__global__ void __launch_bounds__(256, 2)
snn_gemm_kernel(const float* __restrict__ W1) {
    __shared__ float sA2[BK][SA_STRIDE];
    __shared__ float sB[BK][BN];
    __shared__ float sT[BN][68];

    const int tid = threadIdx.x;
    const int s0 = blockIdx.y * BM;
    const int h0 = blockIdx.x * BN;
    const int ty = tid >> 4;
    const int tx = tid & 15;

    unsigned long long acc2[4][2];
#pragma unroll
    for (int i = 0; i < 4; i++) { acc2[i][0] = 0ull; acc2[i][1] = 0ull; }

    for (int k0 = 0; k0 < EMBED; k0 += BK) {
#pragma unroll
        for (int l = 0; l < 2; l++) {
            int f   = tid + l * 256;
            int row = f >> 3;
            int c4  = f & 7;
            float4 v = *reinterpret_cast<const float4*>(
                &g_xm[(size_t)(s0 + row) * EMBED + k0 + c4 * 4]);
            int kk = c4 * 4;
            *reinterpret_cast<float2*>(&sA2[kk + 0][2 * row]) = make_float2(v.x, v.x);
            *reinterpret_cast<float2*>(&sA2[kk + 1][2 * row]) = make_float2(v.y, v.y);
            *reinterpret_cast<float2*>(&sA2[kk + 2][2 * row]) = make_float2(v.z, v.z);
            *reinterpret_cast<float2*>(&sA2[kk + 3][2 * row]) = make_float2(v.w, v.w);
        }
#pragma unroll
        for (int l = 0; l < 2; l++) {
            int f  = tid + l * 256;
            int r  = f >> 4;
            int c4 = f & 15;
            *reinterpret_cast<float4*>(&sB[r][c4 * 4]) =
                *reinterpret_cast<const float4*>(&W1[(size_t)(k0 + r) * HID + h0 + c4 * 4]);
        }
        __syncthreads();

#pragma unroll
        for (int k = 0; k < BK; k++) {
            ulonglong2 a01 = *reinterpret_cast<const ulonglong2*>(&sA2[k][ty * 8]);
            ulonglong2 a23 = *reinterpret_cast<const ulonglong2*>(&sA2[k][ty * 8 + 4]);
            ulonglong2 b   = *reinterpret_cast<const ulonglong2*>(&sB[k][tx * 4]);
            fma2(acc2[0][0], a01.x, b.x); fma2(acc2[0][1], a01.x, b.y);
            fma2(acc2[1][0], a01.y, b.x); fma2(acc2[1][1], a01.y, b.y);
            fma2(acc2[2][0], a23.x, b.x); fma2(acc2[2][1], a23.x, b.y);
            fma2(acc2[3][0], a23.y, b.x); fma2(acc2[3][1], a23.y, b.y);
        }
        __syncthreads();
    }

#pragma unroll
    for (int i = 0; i < 4; i++) {
#pragma unroll
        for (int jp = 0; jp < 2; jp++) {
            float2 v = *reinterpret_cast<float2*>(&acc2[i][jp]);
            sT[tx * 4 + jp * 2 + 0][ty * 4 + i] = v.x;
            sT[tx * 4 + jp * 2 + 1][ty * 4 + i] = v.y;
        }
    }
    __syncthreads();
#pragma unroll
    for (int l = 0; l < 4; l++) {
        int f   = tid + l * 256;
        int row = f >> 4;
        int c4  = f & 15;
        float4 v = *reinterpret_cast<float4*>(&sT[row][c4 * 4]);
        *reinterpret_cast<float4*>(
            &g_curT[(size_t)(h0 + row) * SEQ + s0 + c4 * 4]) = v;
    }
}

// ---------------------------------------------------------------------------
// Kernel 3: windowed epoch-parallel LIF scan. One block per hidden unit.
// Window L=512: P[j] = sum_{i<=j} c_i * d^{-i} (local), Q[j] = P[j] - d^{-j}.
// Membrane from start a (mem=0): m_j = d^j (P[j]-P[a-1]); spike <=> Q[j] >= P[a-1].
// Entering a window with membrane m0: spike <=> Q[j] >= -d*m0.
// Chunk(32)/window(512) maxima of Q bound every search; pointer doubling totals.
// ---------------------------------------------------------------------------
#define DECAYF 0.95f
#define LOG2_INV_D 0.07400058144377693f   // log2(1/0.95)

__global__ void __launch_bounds__(1024, 1)
snn_table_kernel(void) {
    __shared__ float    sQ[SEQ];       // P during build, then Q; Pb in phase 2
    __shared__ float    dinv[512];     // d^{-j}
    __shared__ float    wsum[32];
    __shared__ float    cmax[128];     // per-32-chunk max of Q
    __shared__ float    wmax[8];       // per-window max of Q
    __shared__ float    pend[8];       // P[w*512+511]
    __shared__ unsigned Pa[SEQ + 1];

    const int h    = blockIdx.x;
    const int tid  = threadIdx.x;
    const int lane = tid & 31;
    const int warp = tid >> 5;

    if (tid < 512) dinv[tid] = exp2f((float)tid * LOG2_INV_D);
    __syncthreads();

    // ---- build P (per-window inclusive prefix of c_i * d^{-i}) ----
    const int e = tid * 4;
    float4 c4 = reinterpret_cast<const float4*>(&g_curT[(size_t)h * SEQ])[tid];
    const int jl = e & 511;
    float p0 = c4.x * dinv[jl];
    float p1 = p0 + c4.y * dinv[jl + 1];
    float p2 = p1 + c4.z * dinv[jl + 2];
    float p3 = p2 + c4.w * dinv[jl + 3];
    float ts = p3, sc = p3;
#pragma unroll
    for (int off = 1; off < 32; off <<= 1) {
        float v = __shfl_up_sync(0xffffffffu, sc, off);
        if (lane >= off) sc += v;
    }
    if (lane == 31) wsum[warp] = sc;
    __syncthreads();
    float woff = 0.f;
    const int w0 = warp & ~3;           // first warp of this 128-thread window
    for (int w = w0; w < warp; w++) woff += wsum[w];
    const float excl = sc - ts + woff;
    sQ[e + 0] = p0 + excl; sQ[e + 1] = p1 + excl;
    sQ[e + 2] = p2 + excl; sQ[e + 3] = p3 + excl;
    __syncthreads();

    if (tid < 8) pend[tid] = sQ[tid * 512 + 511];
    __syncthreads();

    // ---- convert to Q in place, build chunk/window maxima ----
    float q0 = sQ[e + 0] - dinv[jl];
    float q1 = sQ[e + 1] - dinv[jl + 1];
    float q2 = sQ[e + 2] - dinv[jl + 2];
    float q3 = sQ[e + 3] - dinv[jl + 3];
    sQ[e + 0] = q0; sQ[e + 1] = q1; sQ[e + 2] = q2; sQ[e + 3] = q3;
    float cm = fmaxf(fmaxf(q0, q1), fmaxf(q2, q3));
#pragma unroll
    for (int off = 1; off < 8; off <<= 1)
        cm = fmaxf(cm, __shfl_xor_sync(0xffffffffu, cm, off));
    if ((tid & 7) == 0) cmax[tid >> 3] = cm;
    __syncthreads();
    if (tid < 8) {
        float m = cmax[tid * 16];
#pragma unroll
        for (int k = 1; k < 16; k++) m = fmaxf(m, cmax[tid * 16 + k]);
        wmax[tid] = m;
    }
    __syncthreads();

    const float dp511 = 1.0f / dinv[511];   // d^511

    // ---- next-spike for every start a (4 per thread, strided) ----
#pragma unroll 1
    for (int r = 0; r < 4; r++) {
        const int a = tid + r * 1024;
        const int w = a >> 9;
        const int j = a & 511;
        float x = (j == 0) ? 0.f : (sQ[(w << 9) + j - 1] + dinv[j - 1]);

        int t = -1;
        {   // search window w from local j
            const int base = w << 9;
            const int cj = j >> 5;
            const int iend = base + ((cj + 1) << 5);
            for (int i = base + j; i < iend; i++)
                if (sQ[i] >= x) { t = i; break; }
            if (t < 0) {
                for (int c = cj + 1; c < 16; c++) {
                    if (cmax[(w << 4) + c] >= x) {
                        int b2 = base + (c << 5);
                        for (int i = b2; i < b2 + 32; i++)
                            if (sQ[i] >= x) { t = i; break; }
                        break;   // hit guaranteed when cmax >= x
                    }
                }
            }
        }
        if (t < 0) {
            float m = dp511 * (pend[w] - x);   // membrane at end of window w
            for (int w2 = w + 1; w2 < 8; w2++) {
                const float x2 = -DECAYF * m;
                if (wmax[w2] >= x2) {
                    const int base = w2 << 9;
                    for (int c = 0; c < 16; c++) {
                        if (cmax[(w2 << 4) + c] >= x2) {
                            int b2 = base + (c << 5);
                            for (int i = b2; i < b2 + 32; i++)
                                if (sQ[i] >= x2) { t = i; break; }
                            break;
                        }
                    }
                    break;      // hit guaranteed when wmax >= x2
                }
                m = dp511 * (DECAYF * m + pend[w2]);
            }
        }
        unsigned pk;
        if (t < 0) pk = (unsigned)SEQ;
        else {
            int jmp = t + 3; if (jmp > SEQ) jmp = SEQ;
            pk = (1u << 13) | (unsigned)jmp;
        }
        Pa[a] = pk;
    }
    if (tid == 0) Pa[SEQ] = (unsigned)SEQ;
    __syncthreads();

    // ---- pointer doubling (12 rounds; chain <= 1366) ----
    unsigned* Pb   = reinterpret_cast<unsigned*>(sQ);
    unsigned* srcp = Pa;
    unsigned* dstp = Pb;
#pragma unroll 1
    for (int r = 0; r < 12; r++) {
        for (int a = tid; a <= SEQ; a += 1024) {
            unsigned p = srcp[a];
            unsigned q = srcp[p & 8191u];
            dstp[a] = ((p & ~8191u) + (q & ~8191u)) | (q & 8191u);
        }
        __syncthreads();
        unsigned* tmp = srcp; srcp = dstp; dstp = tmp;
    }
    if (tid == 0) g_cnt[h] = (float)(srcp[0] >> 13);
}

// ---------------------------------------------------------------------------
// Kernel 4: out = (cnt @ W2) / SEQ. One block per batch row (32 blocks).
// ---------------------------------------------------------------------------
__global__ void __launch_bounds__(128, 1)
snn_out_kernel(const float* __restrict__ W2, float* __restrict__ out) {
    __shared__ float scnt[HID];
    const int b   = blockIdx.x;
    const int tid = threadIdx.x;
    scnt[tid]       = g_cnt[tid];
    scnt[tid + 128] = g_cnt[tid + 128];
    __syncthreads();
    float a = 0.f;
#pragma unroll 16
    for (int k = 0; k < HID; k++)
        a += scnt[k] * W2[(size_t)k * OUTD + tid];
    out[(size_t)b * OUTD + tid] = a * (1.0f / (float)SEQ);
}

// ---------------------------------------------------------------------------
extern "C" void kernel_launch(void* const* d_in, const int* in_sizes, int n_in,
                              void* d_out, int out_size) {
    const float* x  = (const float*)d_in[0];   // [32][4096][512]
    const float* w1 = (const float*)d_in[1];   // [512][256]
    const float* w2 = (const float*)d_in[2];   // [256][128]
    float* out = (float*)d_out;                // [32][128]

    snn_mean_kernel<<<(SEQ * EMBED / 4 + 255) / 256, 256>>>(x);
    snn_gemm_kernel<<<dim3(HID / BN, SEQ / BM), 256>>>(w1);
    snn_table_kernel<<<HID, 1024>>>();
    snn_out_kernel<<<BATCH, OUTD>>>(w2, out);
}

// round 5
// speedup vs baseline: 2.5622x; 2.4270x over previous
#include <cuda_runtime.h>
#include <cuda_bf16.h>

#define BATCH 32
#define SEQ   4096
#define EMBED 512
#define HID   256
#define OUTD  128
#define DECAYF 0.95f
#define LOG2_INV_D 0.07400058144377693f   // log2(1/0.95)

__device__ float    g_xm[SEQ * EMBED];    // batch-mean [4096][512]
__device__ float    g_curT[HID * SEQ];    // currents TRANSPOSED [256][4096]
__device__ float    g_cnt[HID];           // spike counts
__device__ unsigned g_done;               // last-block flag (self-resetting)

// ---------------------------------------------------------------------------
// Kernel 1: batch mean over B=32 (82% of HBM — keep).
// ---------------------------------------------------------------------------
__global__ void snn_mean_kernel(const float* __restrict__ x) {
    const int NF4 = (SEQ * EMBED) / 4;
    int i = blockIdx.x * blockDim.x + threadIdx.x;
    if (i >= NF4) return;
    const float4* x4 = reinterpret_cast<const float4*>(x);
    float sx = 0.f, sy = 0.f, sz = 0.f, sw = 0.f;
#pragma unroll
    for (int b = 0; b < BATCH; b++) {
        float4 v = x4[(size_t)b * NF4 + i];
        sx += v.x; sy += v.y; sz += v.z; sw += v.w;
    }
    const float inv = 1.0f / 32.0f;
    float4 r; r.x = sx * inv; r.y = sy * inv; r.z = sz * inv; r.w = sw * inv;
    reinterpret_cast<float4*>(g_xm)[i] = r;
}

// ---------------------------------------------------------------------------
// Kernel 2: SGEMM currents^T = (xm @ W1)^T.
// 64(s) x 128(h) tile, 128 threads, 8x8 micro-tile, n-packed f32x2,
// cp.async double-buffered. Grid (2, 64) = 128 blocks.
// ---------------------------------------------------------------------------
#define GBM 64
#define GBN 128
#define GBK 32
#define APITCH 36                 // floats per A row (144B, 16B-aligned, odd/4)
#define SA_SZ (GBM * APITCH)      // 2304 floats
#define SB_SZ (GBK * GBN)         // 4096 floats
// gsm layout (floats): sA0 @0, sA1 @2304, sB0 @4608, sB1 @8704; total 12800
#define GEMM_SMEM_BYTES (12800 * 4)

typedef unsigned long long ull;

__device__ __forceinline__ void fma2(ull& d, ull a, ull b) {
    asm("fma.rn.f32x2 %0, %1, %2, %0;" : "+l"(d) : "l"(a), "l"(b));
}
__device__ __forceinline__ ull dup2(float a) {
    ull r;
    asm("mov.b64 %0, {%1, %1};" : "=l"(r) : "f"(a));
    return r;
}
__device__ __forceinline__ void cp16(unsigned dst, const void* src) {
    asm volatile("cp.async.cg.shared.global [%0], [%1], 16;" :: "r"(dst), "l"(src));
}
__device__ __forceinline__ void cp_commit() {
    asm volatile("cp.async.commit_group;");
}
__device__ __forceinline__ void cp_wait0() {
    asm volatile("cp.async.wait_group 0;");
}

__global__ void __launch_bounds__(128, 1)
snn_gemm_kernel(const float* __restrict__ W1) {
    extern __shared__ float gsm[];
    const unsigned smem_u32 = (unsigned)__cvta_generic_to_shared(gsm);

    const int tid = threadIdx.x;
    const int h0  = blockIdx.x * GBN;
    const int s0  = blockIdx.y * GBM;
    const int mgrp = tid >> 4;       // 0..7  -> 8 s-rows
    const int ngrp = tid & 15;       // 0..15 -> 8 h-cols
    const int m0 = mgrp * 8;
    const int n0 = ngrp * 8;

    // async tile loader for chunk c into buffer buf
    auto load_chunk = [&](int c, int buf) {
        const int k0 = c * GBK;
        // A: 64 rows x 32 floats = 512 f4 segments, 4 per thread
        unsigned dA = smem_u32 + (buf * SA_SZ) * 4;
#pragma unroll
        for (int l = 0; l < 4; l++) {
            int f   = tid + l * 128;      // 0..511
            int row = f >> 3;
            int seg = f & 7;
            cp16(dA + (row * APITCH + seg * 4) * 4,
                 &g_xm[(size_t)(s0 + row) * EMBED + k0 + seg * 4]);
        }
        // B: 32 rows x 128 floats = 1024 f4 segments, 8 per thread
        unsigned dB = smem_u32 + (4608 + buf * SB_SZ) * 4;
#pragma unroll
        for (int l = 0; l < 8; l++) {
            int f   = tid + l * 128;      // 0..1023
            int row = f >> 5;
            int seg = f & 31;
            cp16(dB + (row * GBN + seg * 4) * 4,
                 &W1[(size_t)(k0 + row) * HID + h0 + seg * 4]);
        }
        cp_commit();
    };

    ull acc[8][4];
#pragma unroll
    for (int j = 0; j < 8; j++)
#pragma unroll
        for (int p = 0; p < 4; p++) acc[j][p] = 0ull;

    load_chunk(0, 0);

    const int NCHUNK = EMBED / GBK;   // 16
#pragma unroll 1
    for (int c = 0; c < NCHUNK; c++) {
        cp_wait0();
        __syncthreads();
        if (c + 1 < NCHUNK) load_chunk(c + 1, (c + 1) & 1);

        const float* pA = gsm + (c & 1) * SA_SZ + m0 * APITCH;
        const float* pB = gsm + 4608 + (c & 1) * SB_SZ + n0;
#pragma unroll 4
        for (int k = 0; k < GBK; k++) {
            ulonglong2 b01 = *reinterpret_cast<const ulonglong2*>(pB + k * GBN);
            ulonglong2 b23 = *reinterpret_cast<const ulonglong2*>(pB + k * GBN + 4);
#pragma unroll
            for (int j = 0; j < 8; j++) {
                ull ad = dup2(pA[j * APITCH + k]);
                fma2(acc[j][0], ad, b01.x);
                fma2(acc[j][1], ad, b01.y);
                fma2(acc[j][2], ad, b23.x);
                fma2(acc[j][3], ad, b23.y);
            }
        }
        __syncthreads();
    }

    // epilogue: stage transposed [h][s] tile, then coalesced f4 stores
    float* sT = gsm;                  // [128][68] = 8704 floats, fits
#pragma unroll
    for (int j = 0; j < 8; j++) {
#pragma unroll
        for (int p = 0; p < 4; p++) {
            float2 v = *reinterpret_cast<float2*>(&acc[j][p]);
            sT[(n0 + 2 * p + 0) * 68 + (m0 + j)] = v.x;
            sT[(n0 + 2 * p + 1) * 68 + (m0 + j)] = v.y;
        }
    }
    __syncthreads();
#pragma unroll
    for (int l = 0; l < 16; l++) {
        int f    = tid + l * 128;     // 0..2047
        int hrow = f >> 4;
        int seg  = f & 15;
        float4 v = *reinterpret_cast<float4*>(&sT[hrow * 68 + seg * 4]);
        *reinterpret_cast<float4*>(
            &g_curT[(size_t)(h0 + hrow) * SEQ + s0 + seg * 4]) = v;
    }
}

// ---------------------------------------------------------------------------
// Kernel 3: warp-sequential LIF scan + fused output projection.
// 64 blocks x 128 threads; warp w handles unit h = 4*blockIdx + w.
// Per 32-step window: P_t = sum_{i<=t} c_i d^{-i} (warp prefix scan),
// membrane m_t = d^t (P_t - X); spike <=> Q_t = P_t - d^{-t} >= X.
// After spike at ts: restart o = ts+3, X = P_{ts+2}. Window carry:
// no spike -> X' = -d * m31; boundary spike -> reset at next window o',
// X' = P'_{o'-1}. Last finishing block computes out = cnt@W2/SEQ.
// ---------------------------------------------------------------------------
__global__ void __launch_bounds__(128, 1)
snn_table_out_kernel(const float* __restrict__ W2, float* __restrict__ out) {
    extern __shared__ float scs[];    // 4 rows x 4096 floats = 64 KB
    __shared__ unsigned slast;

    const int tid  = threadIdx.x;
    const int lane = tid & 31;
    const int w    = tid >> 5;
    const int hbase = blockIdx.x * 4;

    // stage 4 contiguous unit rows (coalesced float4)
    const float4* src = reinterpret_cast<const float4*>(&g_curT[(size_t)hbase * SEQ]);
#pragma unroll
    for (int l = 0; l < 32; l++)
        reinterpret_cast<float4*>(scs)[tid + l * 128] = src[tid + l * 128];
    __syncthreads();

    const float dinv = exp2f((float)lane * LOG2_INV_D);   // d^{-lane}
    const float d31  = exp2f(-31.0f * LOG2_INV_D);        // d^31

    const float* row = &scs[w * SEQ];
    float X = 0.f;          // threshold on Q for current window
    int   o = 0;            // first active lane in window
    int   carry_bnd = 0, carry_o = 0;
    int   cnt = 0;

#pragma unroll 1
    for (int win = 0; win < SEQ / 32; win++) {
        float c = row[win * 32 + lane];
        float p = c * dinv;
#pragma unroll
        for (int off = 1; off < 32; off <<= 1) {
            float v = __shfl_up_sync(0xffffffffu, p, off);
            if (lane >= off) p += v;
        }
        const float Q   = p - dinv;
        const float P31 = __shfl_sync(0xffffffffu, p, 31);

        if (carry_bnd) {
            o = carry_o;
            X = (carry_o == 0) ? 0.f : __shfl_sync(0xffffffffu, p, carry_o - 1);
            carry_bnd = 0;
        }

        for (;;) {
            unsigned mask = __ballot_sync(0xffffffffu, (Q >= X) && (lane >= o));
            if (!mask) {
                float m31 = d31 * (P31 - X);   // membrane at window end
                X = -DECAYF * m31;             // next window, INIT mode
                o = 0;
                break;
            }
            int ts = __ffs(mask) - 1;
            cnt++;
            if (ts >= 29) {                    // restart lands in next window
                carry_bnd = 1;
                carry_o = ts - 29;             // (ts+3) - 32 in {0,1,2}
                break;
            }
            o = ts + 3;
            X = __shfl_sync(0xffffffffu, p, ts + 2);
        }
    }

    if (lane == 0) g_cnt[hbase + w] = (float)cnt;
    __syncthreads();
    __threadfence();
    if (tid == 0) slast = atomicAdd(&g_done, 1u);
    __syncthreads();

    if (slast == 63) {                         // last of 64 blocks
        __threadfence();
        volatile float* vc = g_cnt;
        float a = 0.f;
#pragma unroll 16
        for (int k = 0; k < HID; k++)
            a += vc[k] * W2[(size_t)k * OUTD + tid];
        a *= (1.0f / (float)SEQ);
#pragma unroll
        for (int b = 0; b < BATCH; b++)
            out[(size_t)b * OUTD + tid] = a;
        __threadfence();
        if (tid == 0) g_done = 0;              // reset for next replay
    }
}

// ---------------------------------------------------------------------------
extern "C" void kernel_launch(void* const* d_in, const int* in_sizes, int n_in,
                              void* d_out, int out_size) {
    const float* x  = (const float*)d_in[0];   // [32][4096][512]
    const float* w1 = (const float*)d_in[1];   // [512][256]
    const float* w2 = (const float*)d_in[2];   // [256][128]
    float* out = (float*)d_out;                // [32][128]

    cudaFuncSetAttribute(snn_gemm_kernel,
                         cudaFuncAttributeMaxDynamicSharedMemorySize,
                         GEMM_SMEM_BYTES);
    cudaFuncSetAttribute(snn_table_out_kernel,
                         cudaFuncAttributeMaxDynamicSharedMemorySize,
                         4 * SEQ * (int)sizeof(float));

    snn_mean_kernel<<<(SEQ * EMBED / 4 + 255) / 256, 256>>>(x);
    snn_gemm_kernel<<<dim3(HID / GBN, SEQ / GBM), 128, GEMM_SMEM_BYTES>>>(w1);
    snn_table_out_kernel<<<HID / 4, 128, 4 * SEQ * sizeof(float)>>>(w2, out);
}